// round 14
// baseline (speedup 1.0000x reference)
#include <cuda_runtime.h>
#include <cuda_fp16.h>
#include <math.h>
#include <stdint.h>

// Problem constants
#define BB 8
#define NN 2048
#define FF 128
#define TJ 64            // j-tile per iteration in k3
#define SRD32 48         // smem row stride (uint32): quad-stride 12 = 4 mod 8 -> conflict-free

typedef unsigned long long ull;

// -------- device scratch --------
__device__ uint32_t g_WhT32[BB * FF * NN / 2];  // [b][f][j/2] half2, sigma-permuted, 4MB
__device__ uint32_t g_adjB[NN * NN / 32];       // sigma-ordered adjacency bitmask, 512KB
__device__ float g_f1[BB * NN];
__device__ float g_f2[BB * NN];                 // j-permuted
__device__ float g_E1p[BB * NN];
__device__ float g_E1n[BB * NN];
__device__ uint32_t g_E2h2[BB * NN];            // j-permuted, half2(E2p, E2n)

// ======================= helpers =======================
__device__ __forceinline__ ull pk2(float lo, float hi) {
    ull d;
    asm("mov.b64 %0, {%1, %2};" : "=l"(d) : "r"(__float_as_uint(lo)), "r"(__float_as_uint(hi)));
    return d;
}
__device__ __forceinline__ void upk2(ull v, float& lo, float& hi) {
    unsigned a, b;
    asm("mov.b64 {%0, %1}, %2;" : "=r"(a), "=r"(b) : "l"(v));
    lo = __uint_as_float(a); hi = __uint_as_float(b);
}
__device__ __forceinline__ ull pfma(ull a, ull b, ull c) {
    ull d;
    asm("fma.rn.f32x2 %0, %1, %2, %3;" : "=l"(d) : "l"(a), "l"(b), "l"(c));
    return d;
}
// pack two f32 -> half2 (lo -> low half, hi -> high half)
__device__ __forceinline__ uint32_t pkhf(float lo, float hi) {
    __half2 t = __floats2half2_rn(lo, hi);
    return *reinterpret_cast<uint32_t*>(&t);
}
// m16n8k16 f16 MMA, fp32 accumulate
__device__ __forceinline__ void mma16(float* c, uint32_t a0, uint32_t a1, uint32_t a2,
                                      uint32_t a3, uint32_t b0, uint32_t b1) {
    asm volatile(
        "mma.sync.aligned.m16n8k16.row.col.f32.f16.f16.f32 "
        "{%0,%1,%2,%3}, {%4,%5,%6,%7}, {%8,%9}, {%0,%1,%2,%3};"
        : "+f"(c[0]), "+f"(c[1]), "+f"(c[2]), "+f"(c[3])
        : "r"(a0), "r"(a1), "r"(a2), "r"(a3), "r"(b0), "r"(b1));
}
__device__ __forceinline__ uint32_t smem_u32(const void* p) {
    uint32_t a;
    asm("{ .reg .u64 t; cvta.to.shared.u64 t, %1; cvt.u32.u64 %0, t; }" : "=r"(a) : "l"(p));
    return a;
}
__device__ __forceinline__ void cp_async16(uint32_t dst, const void* src) {
    asm volatile("cp.async.cg.shared.global [%0], [%1], 16;" :: "r"(dst), "l"(src));
}
// sigma: physical position of logical j within its 32-group (involution)
__device__ __forceinline__ int sigma32(int j) {
    return (j & ~31) | (8 * ((j >> 1) & 3) + 2 * ((j >> 3) & 3) + (j & 1));
}

// ===================== k_adjB: adjacency -> sigma-ordered bitmask ============
// one warp per (row, 32-j group); lane l samples logical j = sigma(l)
__global__ void k_adjB(const float* __restrict__ adj) {
    int warp = (blockIdx.x * 256 + threadIdx.x) >> 5;  // 0 .. 131071
    int lane = threadIdx.x & 31;
    int row = warp >> 6;
    int grp = warp & 63;
    float v = adj[(size_t)row * NN + grp * 32 + sigma32(lane)];
    uint32_t m = __ballot_sync(0xFFFFFFFFu, v > 0.f);
    if (lane == 0) g_adjB[row * 64 + grp] = m;
}

// ===================== k1: WhT + f1/f2 + exp tables, fully fused =============
// grid 256 (8 b x 32 row-tiles of 64), 256 threads, 2 CTAs/SM
__global__ __launch_bounds__(256, 2) void k1_gemm(const float* __restrict__ h,
                                                  const float* __restrict__ W,
                                                  const float* __restrict__ a) {
    extern __shared__ char smem1[];
    float* Ws = (float*)smem1;            // 64KB (reused for score partials)
    float* hs = (float*)(smem1 + 65536);  // 32KB
    ull* part = (ull*)smem1;              // [64][32] score partials (overlay)

    int tid = threadIdx.x;
    const float* hb = h + (size_t)blockIdx.x * 64 * FF;

    #pragma unroll
    for (int i = tid * 4; i < FF * FF; i += 1024)
        *(float4*)&Ws[i] = *(const float4*)&W[i];
    #pragma unroll
    for (int i = tid * 4; i < 64 * FF; i += 1024)
        *(float4*)&hs[i] = *(const float4*)&hb[i];
    __syncthreads();

    int c0 = (tid & 31) * 4;
    int r0 = (tid >> 5) * 8;      // 8 consecutive j-rows
    ull accA[8], accB[8];
    #pragma unroll
    for (int r = 0; r < 8; r++) { accA[r] = 0ULL; accB[r] = 0ULL; }

    for (int k4 = 0; k4 < FF; k4 += 4) {
        ull wA[4], wB[4];
        #pragma unroll
        for (int s = 0; s < 4; s++) {
            float4 w = *(float4*)&Ws[(k4 + s) * FF + c0];
            wA[s] = pk2(w.x, w.y);
            wB[s] = pk2(w.z, w.w);
        }
        #pragma unroll
        for (int r = 0; r < 8; r++) {
            float4 hv = *(float4*)&hs[(r0 + r) * FF + k4];
            ull h0 = pk2(hv.x, hv.x), h1 = pk2(hv.y, hv.y);
            ull h2 = pk2(hv.z, hv.z), h3 = pk2(hv.w, hv.w);
            accA[r] = pfma(h0, wA[0], accA[r]);
            accB[r] = pfma(h0, wB[0], accB[r]);
            accA[r] = pfma(h1, wA[1], accA[r]);
            accB[r] = pfma(h1, wB[1], accB[r]);
            accA[r] = pfma(h2, wA[2], accA[r]);
            accB[r] = pfma(h2, wB[2], accB[r]);
            accA[r] = pfma(h3, wA[3], accA[r]);
            accB[r] = pfma(h3, wB[3], accB[r]);
        }
    }

    float f0[8], f1v[8], f2v[8], f3[8];
    #pragma unroll
    for (int r = 0; r < 8; r++) {
        upk2(accA[r], f0[r], f1v[r]);
        upk2(accB[r], f2v[r], f3[r]);
    }

    // ---- score partials: sp[r] = sum_e Wh[row][c0+e] * (a1[c0+e], a2[c0+e]) ----
    ull apair[4];
    #pragma unroll
    for (int e = 0; e < 4; e++) apair[e] = pk2(a[c0 + e], a[FF + c0 + e]);
    ull sp[8];
    #pragma unroll
    for (int r = 0; r < 8; r++) {
        ull s = pfma(pk2(f0[r], f0[r]), apair[0], 0ULL);
        s = pfma(pk2(f1v[r], f1v[r]), apair[1], s);
        s = pfma(pk2(f2v[r], f2v[r]), apair[2], s);
        s = pfma(pk2(f3[r], f3[r]), apair[3], s);
        sp[r] = s;
    }

    __syncthreads();  // all threads done reading Ws before overlay
    #pragma unroll
    for (int r = 0; r < 8; r++)
        part[(r0 + r) * 32 + (tid & 31)] = sp[r];

    // ---- WhT global store (no smem involved) ----
    int b = blockIdx.x >> 5;
    int n0 = (blockIdx.x & 31) * 64;
    int bofs = (r0 & 31) >> 3;
    size_t grp32 = ((size_t)(n0 + (r0 & ~31))) >> 1;
    #pragma unroll
    for (int e = 0; e < 4; e++) {
        const float* fe = (e == 0) ? f0 : (e == 1) ? f1v : (e == 2) ? f2v : f3;
        uint32_t* dst = g_WhT32 + (((size_t)b * FF + c0 + e) * NN >> 1) + grp32 + bofs;
        #pragma unroll
        for (int s = 0; s < 4; s++)
            dst[4 * s] = pkhf(fe[2 * s], fe[2 * s + 1]);
    }

    __syncthreads();  // partials visible

    // ---- reduce 32 lanes per row; exps; store score tables ----
    if (tid < 64) {
        const ull* pr = part + tid * 32;
        float s1 = 0.f, s2 = 0.f;
        #pragma unroll
        for (int l = 0; l < 32; l++) {
            float lo, hi;
            upk2(pr[l], lo, hi);
            s1 += lo;
            s2 += hi;
        }
        int rowg = b * NN + n0 + tid;
        g_f1[rowg]  = s1;
        g_E1p[rowg] = expf(s1);
        g_E1n[rowg] = expf(0.2f * s1);
        int pj = b * NN + sigma32(n0 + tid);
        g_f2[pj]   = s2;
        g_E2h2[pj] = pkhf(expf(s2), expf(0.2f * s2));
    }
}

// ===================== k3: pipelined f16 mma masked-attention GEMM ===========
// 256 threads / 8 warps / 64 i-rows per CTA; 2 CTAs per SM; grid 256.
// smem (uint32 words): whts0@0(6144), whts1@6144, u0@12288(3072), u1@15360,
// ftab@18432(2048), ehtab@20480(2048), z@22528(64), bias@22592(128); tot 22720
#define K3_SMEM (22720 * 4)

// build masked-exp U for TWO rows x 8 phys-j (shared table loads); bit masks
__device__ __forceinline__ void build_u8_pair(
    uint32_t ma, uint32_t mb, const float* ftab, const uint32_t* ehtab, int joff,
    float rf1a, float rEpa, float rEna, float rf1b, float rEpb, float rEnb,
    uint32_t* da, uint32_t* db, float& za, float& zb) {
    uint32_t pka[4], pkb[4];
    #pragma unroll
    for (int g = 0; g < 2; g++) {
        float4 f = *(const float4*)&ftab[joff + g * 4];
        uint4 eh = *(const uint4*)&ehtab[joff + g * 4];
        float ua[4], ub[4];
        #pragma unroll
        for (int e = 0; e < 4; e++) {
            float2 pe = __half22float2(*reinterpret_cast<__half2*>(&(&eh.x)[e]));
            float fv = (&f.x)[e];
            float va = (rf1a + fv > 0.f) ? (rEpa * pe.x) : (rEna * pe.y);
            float vb = (rf1b + fv > 0.f) ? (rEpb * pe.x) : (rEnb * pe.y);
            ua[e] = ((ma >> (g * 4 + e)) & 1u) ? va : 0.f;
            ub[e] = ((mb >> (g * 4 + e)) & 1u) ? vb : 0.f;
        }
        pka[2 * g]     = pkhf(ua[0], ua[1]);
        pka[2 * g + 1] = pkhf(ua[2], ua[3]);
        pkb[2 * g]     = pkhf(ub[0], ub[1]);
        pkb[2 * g + 1] = pkhf(ub[2], ub[3]);
    }
    #pragma unroll
    for (int q = 0; q < 4; q++) {  // sum the fp16-rounded values
        float2 fa = __half22float2(*reinterpret_cast<__half2*>(&pka[q]));
        float2 fb = __half22float2(*reinterpret_cast<__half2*>(&pkb[q]));
        za += fa.x + fa.y;
        zb += fb.x + fb.y;
    }
    *(uint4*)da = make_uint4(pka[0], pka[1], pka[2], pka[3]);
    *(uint4*)db = make_uint4(pkb[0], pkb[1], pkb[2], pkb[3]);
}

__global__ __launch_bounds__(256, 2) void k3_main(const float* __restrict__ bias,
                                                  float* __restrict__ out) {
    extern __shared__ uint32_t smw[];
    uint32_t* whts[2] = { smw, smw + 6144 };
    uint32_t* u_s[2]  = { smw + 12288, smw + 15360 };
    float* ftab      = (float*)(smw + 18432);
    uint32_t* ehtab  = smw + 20480;
    float* z_s       = (float*)(smw + 22528);
    float* bias_s    = (float*)(smw + 22592);

    const int tid = threadIdx.x;
    const int b = blockIdx.x >> 5;
    const int i0 = (blockIdx.x & 31) * 64;
    const int bn = b * NN;

    // ---- per-CTA tables (whole permuted 2048-j range, loaded once) ----
    #pragma unroll
    for (int i = tid * 4; i < NN; i += 1024) {
        *(float4*)&ftab[i] = *(const float4*)&g_f2[bn + i];
        *(uint4*)&ehtab[i] = *(const uint4*)&g_E2h2[bn + i];
    }
    if (tid < 128) bias_s[tid] = bias[tid];

    // ---- builder identity: 2 rows, one 8-phys-j octet of the 64-j tile ----
    const int rp = tid >> 3;          // 0..31 (row pair)
    const int oct = tid & 7;          // 0..7
    const int rowa = 2 * rp;
    const float rf1a = g_f1[bn + i0 + rowa],   rf1b = g_f1[bn + i0 + rowa + 1];
    const float rEpa = g_E1p[bn + i0 + rowa],  rEpb = g_E1p[bn + i0 + rowa + 1];
    const float rEna = g_E1n[bn + i0 + rowa],  rEnb = g_E1n[bn + i0 + rowa + 1];
    const uint8_t* adjba = (const uint8_t*)g_adjB + (size_t)(i0 + rowa) * 256 + oct;
    const uint8_t* adjbb = adjba + 256;
    const int doffa = rowa * SRD32 + oct * 4;
    const int doffb = doffa + SRD32;

    // ---- WhT cp.async staging identity: row tid>>1, half tid&1 (16 words) ----
    const uint32_t* whp = g_WhT32 + (((size_t)b * FF + (tid >> 1)) * NN >> 1) + (tid & 1) * 16;
    const int sdo = (tid >> 1) * SRD32 + (tid & 1) * 16;
    const uint32_t wdst[2] = { smem_u32(whts[0]) + sdo * 4, smem_u32(whts[1]) + sdo * 4 };

    // ---- mma identity: 8 warps as 2(M) x 4(N); warp tile 32 x 32 ----
    const int lane = tid & 31, wid = tid >> 5;
    const int mg = wid >> 2, ng = wid & 3;
    const int l4 = lane >> 2, lm = lane & 3;

    float acc[2][4][4] = {};
    float z0 = 0.f, z1 = 0.f;
    uint32_t ma, mb;

    __syncthreads();  // tables staged

    // ---- prologue: stage tile 0 ----
    #pragma unroll
    for (int ch = 0; ch < 4; ch++) cp_async16(wdst[0] + ch * 16, whp + ch * 4);
    asm volatile("cp.async.commit_group;");
    ma = adjba[0];
    mb = adjbb[0];
    build_u8_pair(ma, mb, ftab, ehtab, oct * 8, rf1a, rEpa, rEna, rf1b, rEpb, rEnb,
                  u_s[0] + doffa, u_s[0] + doffb, z0, z1);
    asm volatile("cp.async.wait_group 0;" ::: "memory");
    __syncthreads();

    for (int t = 0; t < 32; t++) {
        const int cur = t & 1, nxt = cur ^ 1;
        const int jb2 = (t + 1) * TJ;

        // ---- issue next tile's loads (async) ----
        if (t < 31) {
            #pragma unroll
            for (int ch = 0; ch < 4; ch++)
                cp_async16(wdst[nxt] + ch * 16, whp + (jb2 >> 1) + ch * 4);
            asm volatile("cp.async.commit_group;");
            ma = adjba[jb2 >> 3];
            mb = adjbb[jb2 >> 3];
        }

        // ---- mma(t): 2 k32 chunks x 2 k16 steps; conflict-free LDS.128 frags ----
        const uint32_t* wb = whts[cur];
        const uint32_t* ub = u_s[cur];
        #pragma unroll
        for (int ch = 0; ch < 2; ch++) {
            const int kc = ch * 16 + lm * 4;
            uint4 bv[4];
            #pragma unroll
            for (int ni = 0; ni < 4; ni++)
                bv[ni] = *(const uint4*)&wb[(ng * 32 + ni * 8 + l4) * SRD32 + kc];
            uint4 alo[2], ahi[2];
            #pragma unroll
            for (int mi = 0; mi < 2; mi++) {
                int row = mg * 32 + mi * 16 + l4;
                alo[mi] = *(const uint4*)&ub[row * SRD32 + kc];
                ahi[mi] = *(const uint4*)&ub[(row + 8) * SRD32 + kc];
            }
            #pragma unroll
            for (int mi = 0; mi < 2; mi++)    // k16 step 0
                #pragma unroll
                for (int ni = 0; ni < 4; ni++)
                    mma16(acc[mi][ni], alo[mi].x, ahi[mi].x, alo[mi].y, ahi[mi].y,
                          bv[ni].x, bv[ni].y);
            #pragma unroll
            for (int mi = 0; mi < 2; mi++)    // k16 step 1
                #pragma unroll
                for (int ni = 0; ni < 4; ni++)
                    mma16(acc[mi][ni], alo[mi].z, ahi[mi].z, alo[mi].w, ahi[mi].w,
                          bv[ni].z, bv[ni].w);
        }

        // ---- convert + store U(t+1) ----
        if (t < 31)
            build_u8_pair(ma, mb, ftab, ehtab, jb2 + oct * 8,
                          rf1a, rEpa, rEna, rf1b, rEpb, rEnb,
                          u_s[nxt] + doffa, u_s[nxt] + doffb, z0, z1);

        asm volatile("cp.async.wait_group 0;" ::: "memory");
        __syncthreads();
    }

    // ---- Z finalize: 8 octet-threads per row-pair are adjacent lanes ----
    #pragma unroll
    for (int o = 1; o < 8; o <<= 1) {
        z0 += __shfl_xor_sync(0xFFFFFFFFu, z0, o);
        z1 += __shfl_xor_sync(0xFFFFFFFFu, z1, o);
    }
    if (oct == 0) { z_s[rowa] = z0; z_s[rowa + 1] = z1; }
    __syncthreads();

    // ---- epilogue: 1/Z, +bias, ELU, store from fragments ----
    #pragma unroll
    for (int mi = 0; mi < 2; mi++) {
        const int r0 = mg * 32 + mi * 16 + l4;
        const float iz0 = 1.0f / z_s[r0];
        const float iz1 = 1.0f / z_s[r0 + 8];
        float* o0 = out + ((size_t)(bn + i0 + r0)) * FF;
        float* o1 = o0 + (size_t)8 * FF;
        #pragma unroll
        for (int ni = 0; ni < 4; ni++) {
            const int col = ng * 32 + ni * 8 + 2 * lm;
            const float b0 = bias_s[col], b1 = bias_s[col + 1];
            float x0 = acc[mi][ni][0] * iz0 + b0;
            float x1 = acc[mi][ni][1] * iz0 + b1;
            float x2 = acc[mi][ni][2] * iz1 + b0;
            float x3 = acc[mi][ni][3] * iz1 + b1;
            x0 = (x0 > 0.f) ? x0 : expm1f(x0);
            x1 = (x1 > 0.f) ? x1 : expm1f(x1);
            x2 = (x2 > 0.f) ? x2 : expm1f(x2);
            x3 = (x3 > 0.f) ? x3 : expm1f(x3);
            *(float2*)&o0[col] = make_float2(x0, x1);
            *(float2*)&o1[col] = make_float2(x2, x3);
        }
    }
}

// ============================== launch ==============================
extern "C" void kernel_launch(void* const* d_in, const int* in_sizes, int n_in,
                              void* d_out, int out_size) {
    const float* h    = (const float*)d_in[0];
    const float* adj  = (const float*)d_in[1];
    const float* W    = (const float*)d_in[2];
    const float* a    = (const float*)d_in[3];
    const float* bias = (const float*)d_in[4];
    float* out = (float*)d_out;

    const int smem1 = 65536 + 32768;
    cudaFuncSetAttribute(k1_gemm, cudaFuncAttributeMaxDynamicSharedMemorySize, smem1);
    cudaFuncSetAttribute(k3_main, cudaFuncAttributeMaxDynamicSharedMemorySize, K3_SMEM);

    // 2048 rows x 64 groups = 131072 warps; 8 warps per 256-thread block
    k_adjB<<<NN * (NN / 32) / 8, 256>>>(adj);
    k1_gemm<<<(BB * NN) / 64, 256, smem1>>>(h, W, a);
    k3_main<<<256, 256, K3_SMEM>>>(bias, out);
}

// round 15
// speedup vs baseline: 1.0516x; 1.0516x over previous
#include <cuda_runtime.h>
#include <cuda_fp16.h>
#include <math.h>
#include <stdint.h>

// Problem constants
#define BB 8
#define NN 2048
#define FF 128
#define TJ 64            // j-tile per iteration in k3
#define SRD32 48         // smem row stride (uint32): quad-stride 12 = 4 mod 8 -> conflict-free

typedef unsigned long long ull;

// -------- device scratch --------
__device__ uint32_t g_WhT32[BB * FF * NN / 2];  // [b][f][j/2] half2, sigma-permuted, 4MB
__device__ uint32_t g_adjB[NN * NN / 32];       // sigma-ordered adjacency bitmask, 512KB
__device__ float g_f1[BB * NN];
__device__ float g_f2[BB * NN];                 // j-permuted
__device__ float g_E1p[BB * NN];
__device__ float g_E1n[BB * NN];
__device__ uint32_t g_E2h2[BB * NN];            // j-permuted, half2(E2p, E2n)

// ======================= helpers =======================
__device__ __forceinline__ ull pk2(float lo, float hi) {
    ull d;
    asm("mov.b64 %0, {%1, %2};" : "=l"(d) : "r"(__float_as_uint(lo)), "r"(__float_as_uint(hi)));
    return d;
}
__device__ __forceinline__ void upk2(ull v, float& lo, float& hi) {
    unsigned a, b;
    asm("mov.b64 {%0, %1}, %2;" : "=r"(a), "=r"(b) : "l"(v));
    lo = __uint_as_float(a); hi = __uint_as_float(b);
}
__device__ __forceinline__ ull pfma(ull a, ull b, ull c) {
    ull d;
    asm("fma.rn.f32x2 %0, %1, %2, %3;" : "=l"(d) : "l"(a), "l"(b), "l"(c));
    return d;
}
// pack two f32 -> half2 (lo -> low half, hi -> high half)
__device__ __forceinline__ uint32_t pkhf(float lo, float hi) {
    __half2 t = __floats2half2_rn(lo, hi);
    return *reinterpret_cast<uint32_t*>(&t);
}
// m16n8k16 f16 MMA, fp32 accumulate
__device__ __forceinline__ void mma16(float* c, uint32_t a0, uint32_t a1, uint32_t a2,
                                      uint32_t a3, uint32_t b0, uint32_t b1) {
    asm volatile(
        "mma.sync.aligned.m16n8k16.row.col.f32.f16.f16.f32 "
        "{%0,%1,%2,%3}, {%4,%5,%6,%7}, {%8,%9}, {%0,%1,%2,%3};"
        : "+f"(c[0]), "+f"(c[1]), "+f"(c[2]), "+f"(c[3])
        : "r"(a0), "r"(a1), "r"(a2), "r"(a3), "r"(b0), "r"(b1));
}
__device__ __forceinline__ uint32_t smem_u32(const void* p) {
    uint32_t a;
    asm("{ .reg .u64 t; cvta.to.shared.u64 t, %1; cvt.u32.u64 %0, t; }" : "=r"(a) : "l"(p));
    return a;
}
__device__ __forceinline__ void cp_async16(uint32_t dst, const void* src) {
    asm volatile("cp.async.cg.shared.global [%0], [%1], 16;" :: "r"(dst), "l"(src));
}
// sigma: physical position of logical j within its 32-group (involution)
__device__ __forceinline__ int sigma32(int j) {
    return (j & ~31) | (8 * ((j >> 1) & 3) + 2 * ((j >> 3) & 3) + (j & 1));
}

// ===================== k_adjB: adjacency -> sigma-ordered bitmask ============
// one warp per (4-row quad, 32-j group); lane l samples logical j = sigma(l)
__global__ void k_adjB(const float* __restrict__ adj) {
    int warp = (blockIdx.x * 256 + threadIdx.x) >> 5;  // 0 .. 32767
    int lane = threadIdx.x & 31;
    int row4 = (warp >> 6) * 4;
    int grp = warp & 63;
    const float* p = adj + (size_t)row4 * NN + grp * 32 + sigma32(lane);
    float v0 = p[0];
    float v1 = p[NN];
    float v2 = p[2 * NN];
    float v3 = p[3 * NN];
    uint32_t m0 = __ballot_sync(0xFFFFFFFFu, v0 > 0.f);
    uint32_t m1 = __ballot_sync(0xFFFFFFFFu, v1 > 0.f);
    uint32_t m2 = __ballot_sync(0xFFFFFFFFu, v2 > 0.f);
    uint32_t m3 = __ballot_sync(0xFFFFFFFFu, v3 > 0.f);
    if (lane < 4) {
        uint32_t m = (lane == 0) ? m0 : (lane == 1) ? m1 : (lane == 2) ? m2 : m3;
        g_adjB[(row4 + lane) * 64 + grp] = m;
    }
}

// ===================== k1: WhT + f1/f2 + exp tables, fully fused =============
// grid 256 (8 b x 32 row-tiles of 64), 256 threads, 2 CTAs/SM
__global__ __launch_bounds__(256, 2) void k1_gemm(const float* __restrict__ h,
                                                  const float* __restrict__ W,
                                                  const float* __restrict__ a) {
    extern __shared__ char smem1[];
    float* Ws = (float*)smem1;            // 64KB (reused for score partials)
    float* hs = (float*)(smem1 + 65536);  // 32KB
    ull* part = (ull*)smem1;              // [64][32] score partials (overlay)

    int tid = threadIdx.x;
    const float* hb = h + (size_t)blockIdx.x * 64 * FF;

    #pragma unroll
    for (int i = tid * 4; i < FF * FF; i += 1024)
        *(float4*)&Ws[i] = *(const float4*)&W[i];
    #pragma unroll
    for (int i = tid * 4; i < 64 * FF; i += 1024)
        *(float4*)&hs[i] = *(const float4*)&hb[i];
    __syncthreads();

    int c0 = (tid & 31) * 4;
    int r0 = (tid >> 5) * 8;      // 8 consecutive j-rows
    ull accA[8], accB[8];
    #pragma unroll
    for (int r = 0; r < 8; r++) { accA[r] = 0ULL; accB[r] = 0ULL; }

    for (int k4 = 0; k4 < FF; k4 += 4) {
        ull wA[4], wB[4];
        #pragma unroll
        for (int s = 0; s < 4; s++) {
            float4 w = *(float4*)&Ws[(k4 + s) * FF + c0];
            wA[s] = pk2(w.x, w.y);
            wB[s] = pk2(w.z, w.w);
        }
        #pragma unroll
        for (int r = 0; r < 8; r++) {
            float4 hv = *(float4*)&hs[(r0 + r) * FF + k4];
            ull h0 = pk2(hv.x, hv.x), h1 = pk2(hv.y, hv.y);
            ull h2 = pk2(hv.z, hv.z), h3 = pk2(hv.w, hv.w);
            accA[r] = pfma(h0, wA[0], accA[r]);
            accB[r] = pfma(h0, wB[0], accB[r]);
            accA[r] = pfma(h1, wA[1], accA[r]);
            accB[r] = pfma(h1, wB[1], accB[r]);
            accA[r] = pfma(h2, wA[2], accA[r]);
            accB[r] = pfma(h2, wB[2], accB[r]);
            accA[r] = pfma(h3, wA[3], accA[r]);
            accB[r] = pfma(h3, wB[3], accB[r]);
        }
    }

    float f0[8], f1v[8], f2v[8], f3[8];
    #pragma unroll
    for (int r = 0; r < 8; r++) {
        upk2(accA[r], f0[r], f1v[r]);
        upk2(accB[r], f2v[r], f3[r]);
    }

    // ---- score partials: sp[r] = sum_e Wh[row][c0+e] * (a1[c0+e], a2[c0+e]) ----
    ull apair[4];
    #pragma unroll
    for (int e = 0; e < 4; e++) apair[e] = pk2(a[c0 + e], a[FF + c0 + e]);
    ull sp[8];
    #pragma unroll
    for (int r = 0; r < 8; r++) {
        ull s = pfma(pk2(f0[r], f0[r]), apair[0], 0ULL);
        s = pfma(pk2(f1v[r], f1v[r]), apair[1], s);
        s = pfma(pk2(f2v[r], f2v[r]), apair[2], s);
        s = pfma(pk2(f3[r], f3[r]), apair[3], s);
        sp[r] = s;
    }

    __syncthreads();  // all threads done reading Ws before overlay
    #pragma unroll
    for (int r = 0; r < 8; r++)
        part[(r0 + r) * 32 + (tid & 31)] = sp[r];

    // ---- WhT global store (no smem involved) ----
    int b = blockIdx.x >> 5;
    int n0 = (blockIdx.x & 31) * 64;
    int bofs = (r0 & 31) >> 3;
    size_t grp32 = ((size_t)(n0 + (r0 & ~31))) >> 1;
    #pragma unroll
    for (int e = 0; e < 4; e++) {
        const float* fe = (e == 0) ? f0 : (e == 1) ? f1v : (e == 2) ? f2v : f3;
        uint32_t* dst = g_WhT32 + (((size_t)b * FF + c0 + e) * NN >> 1) + grp32 + bofs;
        #pragma unroll
        for (int s = 0; s < 4; s++)
            dst[4 * s] = pkhf(fe[2 * s], fe[2 * s + 1]);
    }

    __syncthreads();  // partials visible

    // ---- reduce 32 lanes per row; exps; store score tables ----
    if (tid < 64) {
        const ull* pr = part + tid * 32;
        float s1 = 0.f, s2 = 0.f;
        #pragma unroll
        for (int l = 0; l < 32; l++) {
            float lo, hi;
            upk2(pr[l], lo, hi);
            s1 += lo;
            s2 += hi;
        }
        int rowg = b * NN + n0 + tid;
        g_f1[rowg]  = s1;
        g_E1p[rowg] = expf(s1);
        g_E1n[rowg] = expf(0.2f * s1);
        int pj = b * NN + sigma32(n0 + tid);
        g_f2[pj]   = s2;
        g_E2h2[pj] = pkhf(expf(s2), expf(0.2f * s2));
    }
}

// ===================== k3: pipelined f16 mma masked-attention GEMM ===========
// 256 threads / 8 warps / 64 i-rows per CTA; 2 CTAs per SM; grid 256.
// smem (uint32 words): whts0@0(6144), whts1@6144, u0@12288(3072), u1@15360,
// ftab@18432(2048), ehtab@20480(2048), z@22528(64), bias@22592(128); tot 22720
#define K3_SMEM (22720 * 4)

// build masked-exp U for TWO rows x 8 phys-j (shared table loads); bit masks
__device__ __forceinline__ void build_u8_pair(
    uint32_t ma, uint32_t mb, const float* ftab, const uint32_t* ehtab, int joff,
    float rf1a, float rEpa, float rEna, float rf1b, float rEpb, float rEnb,
    uint32_t* da, uint32_t* db, float& za, float& zb) {
    uint32_t pka[4], pkb[4];
    #pragma unroll
    for (int g = 0; g < 2; g++) {
        float4 f = *(const float4*)&ftab[joff + g * 4];
        uint4 eh = *(const uint4*)&ehtab[joff + g * 4];
        float ua[4], ub[4];
        #pragma unroll
        for (int e = 0; e < 4; e++) {
            float2 pe = __half22float2(*reinterpret_cast<__half2*>(&(&eh.x)[e]));
            float fv = (&f.x)[e];
            float va = (rf1a + fv > 0.f) ? (rEpa * pe.x) : (rEna * pe.y);
            float vb = (rf1b + fv > 0.f) ? (rEpb * pe.x) : (rEnb * pe.y);
            ua[e] = ((ma >> (g * 4 + e)) & 1u) ? va : 0.f;
            ub[e] = ((mb >> (g * 4 + e)) & 1u) ? vb : 0.f;
        }
        pka[2 * g]     = pkhf(ua[0], ua[1]);
        pka[2 * g + 1] = pkhf(ua[2], ua[3]);
        pkb[2 * g]     = pkhf(ub[0], ub[1]);
        pkb[2 * g + 1] = pkhf(ub[2], ub[3]);
    }
    #pragma unroll
    for (int q = 0; q < 4; q++) {  // sum the fp16-rounded values
        float2 fa = __half22float2(*reinterpret_cast<__half2*>(&pka[q]));
        float2 fb = __half22float2(*reinterpret_cast<__half2*>(&pkb[q]));
        za += fa.x + fa.y;
        zb += fb.x + fb.y;
    }
    *(uint4*)da = make_uint4(pka[0], pka[1], pka[2], pka[3]);
    *(uint4*)db = make_uint4(pkb[0], pkb[1], pkb[2], pkb[3]);
}

__global__ __launch_bounds__(256, 2) void k3_main(const float* __restrict__ bias,
                                                  float* __restrict__ out) {
    extern __shared__ uint32_t smw[];
    uint32_t* whts[2] = { smw, smw + 6144 };
    uint32_t* u_s[2]  = { smw + 12288, smw + 15360 };
    float* ftab      = (float*)(smw + 18432);
    uint32_t* ehtab  = smw + 20480;
    float* z_s       = (float*)(smw + 22528);
    float* bias_s    = (float*)(smw + 22592);

    const int tid = threadIdx.x;
    const int b = blockIdx.x >> 5;
    const int i0 = (blockIdx.x & 31) * 64;
    const int bn = b * NN;

    // ---- per-CTA tables (whole permuted 2048-j range, loaded once) ----
    #pragma unroll
    for (int i = tid * 4; i < NN; i += 1024) {
        *(float4*)&ftab[i] = *(const float4*)&g_f2[bn + i];
        *(uint4*)&ehtab[i] = *(const uint4*)&g_E2h2[bn + i];
    }
    if (tid < 128) bias_s[tid] = bias[tid];

    // ---- builder identity: 2 rows, one 8-phys-j octet of the 64-j tile ----
    const int rp = tid >> 3;          // 0..31 (row pair)
    const int oct = tid & 7;          // 0..7
    const int rowa = 2 * rp;
    const float rf1a = g_f1[bn + i0 + rowa],   rf1b = g_f1[bn + i0 + rowa + 1];
    const float rEpa = g_E1p[bn + i0 + rowa],  rEpb = g_E1p[bn + i0 + rowa + 1];
    const float rEna = g_E1n[bn + i0 + rowa],  rEnb = g_E1n[bn + i0 + rowa + 1];
    const uint8_t* adjba = (const uint8_t*)g_adjB + (size_t)(i0 + rowa) * 256 + oct;
    const uint8_t* adjbb = adjba + 256;
    const int doffa = rowa * SRD32 + oct * 4;
    const int doffb = doffa + SRD32;

    // ---- WhT cp.async staging identity: row tid>>1, half tid&1 (16 words) ----
    const uint32_t* whp = g_WhT32 + (((size_t)b * FF + (tid >> 1)) * NN >> 1) + (tid & 1) * 16;
    const int sdo = (tid >> 1) * SRD32 + (tid & 1) * 16;
    const uint32_t wdst[2] = { smem_u32(whts[0]) + sdo * 4, smem_u32(whts[1]) + sdo * 4 };

    // ---- mma identity: 8 warps as 2(M) x 4(N); warp tile 32 x 32 ----
    const int lane = tid & 31, wid = tid >> 5;
    const int mg = wid >> 2, ng = wid & 3;
    const int l4 = lane >> 2, lm = lane & 3;

    float acc[2][4][4] = {};
    float z0 = 0.f, z1 = 0.f;
    uint32_t ma, mb;

    __syncthreads();  // tables staged

    // ---- prologue: stage tile 0 ----
    #pragma unroll
    for (int ch = 0; ch < 4; ch++) cp_async16(wdst[0] + ch * 16, whp + ch * 4);
    asm volatile("cp.async.commit_group;");
    ma = adjba[0];
    mb = adjbb[0];
    build_u8_pair(ma, mb, ftab, ehtab, oct * 8, rf1a, rEpa, rEna, rf1b, rEpb, rEnb,
                  u_s[0] + doffa, u_s[0] + doffb, z0, z1);
    asm volatile("cp.async.wait_group 0;" ::: "memory");
    __syncthreads();

    for (int t = 0; t < 32; t++) {
        const int cur = t & 1, nxt = cur ^ 1;
        const int jb2 = (t + 1) * TJ;

        // ---- issue next tile's loads (async) ----
        if (t < 31) {
            #pragma unroll
            for (int ch = 0; ch < 4; ch++)
                cp_async16(wdst[nxt] + ch * 16, whp + (jb2 >> 1) + ch * 4);
            asm volatile("cp.async.commit_group;");
            ma = adjba[jb2 >> 3];
            mb = adjbb[jb2 >> 3];
        }

        // ---- mma(t): 2 k32 chunks x 2 k16 steps; conflict-free LDS.128 frags ----
        const uint32_t* wb = whts[cur];
        const uint32_t* ub = u_s[cur];
        #pragma unroll
        for (int ch = 0; ch < 2; ch++) {
            const int kc = ch * 16 + lm * 4;
            uint4 bv[4];
            #pragma unroll
            for (int ni = 0; ni < 4; ni++)
                bv[ni] = *(const uint4*)&wb[(ng * 32 + ni * 8 + l4) * SRD32 + kc];
            uint4 alo[2], ahi[2];
            #pragma unroll
            for (int mi = 0; mi < 2; mi++) {
                int row = mg * 32 + mi * 16 + l4;
                alo[mi] = *(const uint4*)&ub[row * SRD32 + kc];
                ahi[mi] = *(const uint4*)&ub[(row + 8) * SRD32 + kc];
            }
            #pragma unroll
            for (int mi = 0; mi < 2; mi++)    // k16 step 0
                #pragma unroll
                for (int ni = 0; ni < 4; ni++)
                    mma16(acc[mi][ni], alo[mi].x, ahi[mi].x, alo[mi].y, ahi[mi].y,
                          bv[ni].x, bv[ni].y);
            #pragma unroll
            for (int mi = 0; mi < 2; mi++)    // k16 step 1
                #pragma unroll
                for (int ni = 0; ni < 4; ni++)
                    mma16(acc[mi][ni], alo[mi].z, ahi[mi].z, alo[mi].w, ahi[mi].w,
                          bv[ni].z, bv[ni].w);
        }

        // ---- convert + store U(t+1) ----
        if (t < 31)
            build_u8_pair(ma, mb, ftab, ehtab, jb2 + oct * 8,
                          rf1a, rEpa, rEna, rf1b, rEpb, rEnb,
                          u_s[nxt] + doffa, u_s[nxt] + doffb, z0, z1);

        asm volatile("cp.async.wait_group 0;" ::: "memory");
        __syncthreads();
    }

    // ---- Z finalize: 8 octet-threads per row-pair are adjacent lanes ----
    #pragma unroll
    for (int o = 1; o < 8; o <<= 1) {
        z0 += __shfl_xor_sync(0xFFFFFFFFu, z0, o);
        z1 += __shfl_xor_sync(0xFFFFFFFFu, z1, o);
    }
    if (oct == 0) { z_s[rowa] = z0; z_s[rowa + 1] = z1; }
    __syncthreads();

    // ---- epilogue: 1/Z, +bias, ELU, store from fragments ----
    #pragma unroll
    for (int mi = 0; mi < 2; mi++) {
        const int r0 = mg * 32 + mi * 16 + l4;
        const float iz0 = 1.0f / z_s[r0];
        const float iz1 = 1.0f / z_s[r0 + 8];
        float* o0 = out + ((size_t)(bn + i0 + r0)) * FF;
        float* o1 = o0 + (size_t)8 * FF;
        #pragma unroll
        for (int ni = 0; ni < 4; ni++) {
            const int col = ng * 32 + ni * 8 + 2 * lm;
            const float b0 = bias_s[col], b1 = bias_s[col + 1];
            float x0 = acc[mi][ni][0] * iz0 + b0;
            float x1 = acc[mi][ni][1] * iz0 + b1;
            float x2 = acc[mi][ni][2] * iz1 + b0;
            float x3 = acc[mi][ni][3] * iz1 + b1;
            x0 = (x0 > 0.f) ? x0 : expm1f(x0);
            x1 = (x1 > 0.f) ? x1 : expm1f(x1);
            x2 = (x2 > 0.f) ? x2 : expm1f(x2);
            x3 = (x3 > 0.f) ? x3 : expm1f(x3);
            *(float2*)&o0[col] = make_float2(x0, x1);
            *(float2*)&o1[col] = make_float2(x2, x3);
        }
    }
}

// ============================== launch ==============================
extern "C" void kernel_launch(void* const* d_in, const int* in_sizes, int n_in,
                              void* d_out, int out_size) {
    const float* h    = (const float*)d_in[0];
    const float* adj  = (const float*)d_in[1];
    const float* W    = (const float*)d_in[2];
    const float* a    = (const float*)d_in[3];
    const float* bias = (const float*)d_in[4];
    float* out = (float*)d_out;

    const int smem1 = 65536 + 32768;
    cudaFuncSetAttribute(k1_gemm, cudaFuncAttributeMaxDynamicSharedMemorySize, smem1);
    cudaFuncSetAttribute(k3_main, cudaFuncAttributeMaxDynamicSharedMemorySize, K3_SMEM);

    // 512 row-quads x 64 groups = 32768 warps; 8 warps per 256-thread block
    k_adjB<<<(NN / 4) * (NN / 32) / 8, 256>>>(adj);
    k1_gemm<<<(BB * NN) / 64, 256, smem1>>>(h, W, a);
    k3_main<<<256, 256, K3_SMEM>>>(bias, out);
}

// round 16
// speedup vs baseline: 1.0694x; 1.0169x over previous
#include <cuda_runtime.h>
#include <cuda_fp16.h>
#include <math.h>
#include <stdint.h>

// Problem constants
#define BB 8
#define NN 2048
#define FF 128
#define TJ 64            // j-tile per iteration in k3
#define SRD32 48         // smem row stride (uint32): quad-stride 12 = 4 mod 8 -> conflict-free

typedef unsigned long long ull;

// -------- device scratch --------
__device__ uint32_t g_WhT32[BB * FF * NN / 2];  // [b][f][j/2] half2, sigma-permuted, 4MB
__device__ uint32_t g_adjB[NN * NN / 32];       // sigma-ordered adjacency bitmask, 512KB
__device__ float g_f1[BB * NN];
__device__ float g_f2[BB * NN];                 // j-permuted
__device__ float g_E1p[BB * NN];
__device__ float g_E1n[BB * NN];
__device__ uint32_t g_E2h2[BB * NN];            // j-permuted, half2(E2p, E2n)

// ======================= helpers =======================
__device__ __forceinline__ ull pk2(float lo, float hi) {
    ull d;
    asm("mov.b64 %0, {%1, %2};" : "=l"(d) : "r"(__float_as_uint(lo)), "r"(__float_as_uint(hi)));
    return d;
}
__device__ __forceinline__ void upk2(ull v, float& lo, float& hi) {
    unsigned a, b;
    asm("mov.b64 {%0, %1}, %2;" : "=r"(a), "=r"(b) : "l"(v));
    lo = __uint_as_float(a); hi = __uint_as_float(b);
}
__device__ __forceinline__ ull pfma(ull a, ull b, ull c) {
    ull d;
    asm("fma.rn.f32x2 %0, %1, %2, %3;" : "=l"(d) : "l"(a), "l"(b), "l"(c));
    return d;
}
// pack two f32 -> half2 (lo -> low half, hi -> high half)
__device__ __forceinline__ uint32_t pkhf(float lo, float hi) {
    __half2 t = __floats2half2_rn(lo, hi);
    return *reinterpret_cast<uint32_t*>(&t);
}
// m16n8k16 f16 MMA, fp32 accumulate
__device__ __forceinline__ void mma16(float* c, uint32_t a0, uint32_t a1, uint32_t a2,
                                      uint32_t a3, uint32_t b0, uint32_t b1) {
    asm volatile(
        "mma.sync.aligned.m16n8k16.row.col.f32.f16.f16.f32 "
        "{%0,%1,%2,%3}, {%4,%5,%6,%7}, {%8,%9}, {%0,%1,%2,%3};"
        : "+f"(c[0]), "+f"(c[1]), "+f"(c[2]), "+f"(c[3])
        : "r"(a0), "r"(a1), "r"(a2), "r"(a3), "r"(b0), "r"(b1));
}
__device__ __forceinline__ uint32_t smem_u32(const void* p) {
    uint32_t a;
    asm("{ .reg .u64 t; cvta.to.shared.u64 t, %1; cvt.u32.u64 %0, t; }" : "=r"(a) : "l"(p));
    return a;
}
__device__ __forceinline__ void cp_async16(uint32_t dst, const void* src) {
    asm volatile("cp.async.cg.shared.global [%0], [%1], 16;" :: "r"(dst), "l"(src));
}
// sigma: physical position of logical j within its 32-group (involution)
__device__ __forceinline__ int sigma32(int j) {
    return (j & ~31) | (8 * ((j >> 1) & 3) + 2 * ((j >> 3) & 3) + (j & 1));
}

// ===================== k_adjB: adjacency -> sigma-ordered bitmask ============
// one warp per (8-row octet, 32-j group); lane l samples logical j = sigma(l).
// All 8 loads issued before any ballot -> MLP = 8.
__global__ void k_adjB(const float* __restrict__ adj) {
    int warp = (blockIdx.x * 256 + threadIdx.x) >> 5;  // 0 .. 16383
    int lane = threadIdx.x & 31;
    int row8 = (warp >> 6) * 8;
    int grp = warp & 63;
    const float* p = adj + (size_t)row8 * NN + grp * 32 + sigma32(lane);
    float v[8];
    #pragma unroll
    for (int r = 0; r < 8; r++) v[r] = p[(size_t)r * NN];
    uint32_t m[8];
    #pragma unroll
    for (int r = 0; r < 8; r++) m[r] = __ballot_sync(0xFFFFFFFFu, v[r] > 0.f);
    if (lane < 8) {
        uint32_t mv = m[0];
        mv = (lane == 1) ? m[1] : mv;
        mv = (lane == 2) ? m[2] : mv;
        mv = (lane == 3) ? m[3] : mv;
        mv = (lane == 4) ? m[4] : mv;
        mv = (lane == 5) ? m[5] : mv;
        mv = (lane == 6) ? m[6] : mv;
        mv = (lane == 7) ? m[7] : mv;
        g_adjB[(row8 + lane) * 64 + grp] = mv;
    }
}

// ===================== k1: WhT + f1/f2 + exp tables, fully fused =============
// grid 256 (8 b x 32 row-tiles of 64), 256 threads, 2 CTAs/SM
__global__ __launch_bounds__(256, 2) void k1_gemm(const float* __restrict__ h,
                                                  const float* __restrict__ W,
                                                  const float* __restrict__ a) {
    extern __shared__ char smem1[];
    float* Ws = (float*)smem1;            // 64KB (reused for score partials)
    float* hs = (float*)(smem1 + 65536);  // 32KB
    ull* part = (ull*)smem1;              // [64][32] score partials (overlay)

    int tid = threadIdx.x;
    const float* hb = h + (size_t)blockIdx.x * 64 * FF;

    #pragma unroll
    for (int i = tid * 4; i < FF * FF; i += 1024)
        *(float4*)&Ws[i] = *(const float4*)&W[i];
    #pragma unroll
    for (int i = tid * 4; i < 64 * FF; i += 1024)
        *(float4*)&hs[i] = *(const float4*)&hb[i];
    __syncthreads();

    int c0 = (tid & 31) * 4;
    int r0 = (tid >> 5) * 8;      // 8 consecutive j-rows
    ull accA[8], accB[8];
    #pragma unroll
    for (int r = 0; r < 8; r++) { accA[r] = 0ULL; accB[r] = 0ULL; }

    for (int k4 = 0; k4 < FF; k4 += 4) {
        ull wA[4], wB[4];
        #pragma unroll
        for (int s = 0; s < 4; s++) {
            float4 w = *(float4*)&Ws[(k4 + s) * FF + c0];
            wA[s] = pk2(w.x, w.y);
            wB[s] = pk2(w.z, w.w);
        }
        #pragma unroll
        for (int r = 0; r < 8; r++) {
            float4 hv = *(float4*)&hs[(r0 + r) * FF + k4];
            ull h0 = pk2(hv.x, hv.x), h1 = pk2(hv.y, hv.y);
            ull h2 = pk2(hv.z, hv.z), h3 = pk2(hv.w, hv.w);
            accA[r] = pfma(h0, wA[0], accA[r]);
            accB[r] = pfma(h0, wB[0], accB[r]);
            accA[r] = pfma(h1, wA[1], accA[r]);
            accB[r] = pfma(h1, wB[1], accB[r]);
            accA[r] = pfma(h2, wA[2], accA[r]);
            accB[r] = pfma(h2, wB[2], accB[r]);
            accA[r] = pfma(h3, wA[3], accA[r]);
            accB[r] = pfma(h3, wB[3], accB[r]);
        }
    }

    float f0[8], f1v[8], f2v[8], f3[8];
    #pragma unroll
    for (int r = 0; r < 8; r++) {
        upk2(accA[r], f0[r], f1v[r]);
        upk2(accB[r], f2v[r], f3[r]);
    }

    // ---- score partials: sp[r] = sum_e Wh[row][c0+e] * (a1[c0+e], a2[c0+e]) ----
    ull apair[4];
    #pragma unroll
    for (int e = 0; e < 4; e++) apair[e] = pk2(a[c0 + e], a[FF + c0 + e]);
    ull sp[8];
    #pragma unroll
    for (int r = 0; r < 8; r++) {
        ull s = pfma(pk2(f0[r], f0[r]), apair[0], 0ULL);
        s = pfma(pk2(f1v[r], f1v[r]), apair[1], s);
        s = pfma(pk2(f2v[r], f2v[r]), apair[2], s);
        s = pfma(pk2(f3[r], f3[r]), apair[3], s);
        sp[r] = s;
    }

    __syncthreads();  // all threads done reading Ws before overlay
    #pragma unroll
    for (int r = 0; r < 8; r++)
        part[(r0 + r) * 32 + (tid & 31)] = sp[r];

    // ---- WhT global store (no smem involved) ----
    int b = blockIdx.x >> 5;
    int n0 = (blockIdx.x & 31) * 64;
    int bofs = (r0 & 31) >> 3;
    size_t grp32 = ((size_t)(n0 + (r0 & ~31))) >> 1;
    #pragma unroll
    for (int e = 0; e < 4; e++) {
        const float* fe = (e == 0) ? f0 : (e == 1) ? f1v : (e == 2) ? f2v : f3;
        uint32_t* dst = g_WhT32 + (((size_t)b * FF + c0 + e) * NN >> 1) + grp32 + bofs;
        #pragma unroll
        for (int s = 0; s < 4; s++)
            dst[4 * s] = pkhf(fe[2 * s], fe[2 * s + 1]);
    }

    __syncthreads();  // partials visible

    // ---- reduce 32 lanes per row; exps; store score tables ----
    if (tid < 64) {
        const ull* pr = part + tid * 32;
        float s1 = 0.f, s2 = 0.f;
        #pragma unroll
        for (int l = 0; l < 32; l++) {
            float lo, hi;
            upk2(pr[l], lo, hi);
            s1 += lo;
            s2 += hi;
        }
        int rowg = b * NN + n0 + tid;
        g_f1[rowg]  = s1;
        g_E1p[rowg] = expf(s1);
        g_E1n[rowg] = expf(0.2f * s1);
        int pj = b * NN + sigma32(n0 + tid);
        g_f2[pj]   = s2;
        g_E2h2[pj] = pkhf(expf(s2), expf(0.2f * s2));
    }
}

// ===================== k3: pipelined f16 mma masked-attention GEMM ===========
// 256 threads / 8 warps / 64 i-rows per CTA; 2 CTAs per SM; grid 256.
// smem (uint32 words): whts0@0(6144), whts1@6144, u0@12288(3072), u1@15360,
// ftab@18432(2048), ehtab@20480(2048), z@22528(64), bias@22592(128); tot 22720
#define K3_SMEM (22720 * 4)

// build masked-exp U for TWO rows x 8 phys-j (shared table loads); bit masks
__device__ __forceinline__ void build_u8_pair(
    uint32_t ma, uint32_t mb, const float* ftab, const uint32_t* ehtab, int joff,
    float rf1a, float rEpa, float rEna, float rf1b, float rEpb, float rEnb,
    uint32_t* da, uint32_t* db, float& za, float& zb) {
    uint32_t pka[4], pkb[4];
    #pragma unroll
    for (int g = 0; g < 2; g++) {
        float4 f = *(const float4*)&ftab[joff + g * 4];
        uint4 eh = *(const uint4*)&ehtab[joff + g * 4];
        float ua[4], ub[4];
        #pragma unroll
        for (int e = 0; e < 4; e++) {
            float2 pe = __half22float2(*reinterpret_cast<__half2*>(&(&eh.x)[e]));
            float fv = (&f.x)[e];
            float va = (rf1a + fv > 0.f) ? (rEpa * pe.x) : (rEna * pe.y);
            float vb = (rf1b + fv > 0.f) ? (rEpb * pe.x) : (rEnb * pe.y);
            ua[e] = ((ma >> (g * 4 + e)) & 1u) ? va : 0.f;
            ub[e] = ((mb >> (g * 4 + e)) & 1u) ? vb : 0.f;
        }
        pka[2 * g]     = pkhf(ua[0], ua[1]);
        pka[2 * g + 1] = pkhf(ua[2], ua[3]);
        pkb[2 * g]     = pkhf(ub[0], ub[1]);
        pkb[2 * g + 1] = pkhf(ub[2], ub[3]);
    }
    #pragma unroll
    for (int q = 0; q < 4; q++) {  // sum the fp16-rounded values
        float2 fa = __half22float2(*reinterpret_cast<__half2*>(&pka[q]));
        float2 fb = __half22float2(*reinterpret_cast<__half2*>(&pkb[q]));
        za += fa.x + fa.y;
        zb += fb.x + fb.y;
    }
    *(uint4*)da = make_uint4(pka[0], pka[1], pka[2], pka[3]);
    *(uint4*)db = make_uint4(pkb[0], pkb[1], pkb[2], pkb[3]);
}

__global__ __launch_bounds__(256, 2) void k3_main(const float* __restrict__ bias,
                                                  float* __restrict__ out) {
    extern __shared__ uint32_t smw[];
    uint32_t* whts[2] = { smw, smw + 6144 };
    uint32_t* u_s[2]  = { smw + 12288, smw + 15360 };
    float* ftab      = (float*)(smw + 18432);
    uint32_t* ehtab  = smw + 20480;
    float* z_s       = (float*)(smw + 22528);
    float* bias_s    = (float*)(smw + 22592);

    const int tid = threadIdx.x;
    const int b = blockIdx.x >> 5;
    const int i0 = (blockIdx.x & 31) * 64;
    const int bn = b * NN;

    // ---- per-CTA tables (whole permuted 2048-j range, loaded once) ----
    #pragma unroll
    for (int i = tid * 4; i < NN; i += 1024) {
        *(float4*)&ftab[i] = *(const float4*)&g_f2[bn + i];
        *(uint4*)&ehtab[i] = *(const uint4*)&g_E2h2[bn + i];
    }
    if (tid < 128) bias_s[tid] = bias[tid];

    // ---- builder identity: 2 rows, one 8-phys-j octet of the 64-j tile ----
    const int rp = tid >> 3;          // 0..31 (row pair)
    const int oct = tid & 7;          // 0..7
    const int rowa = 2 * rp;
    const float rf1a = g_f1[bn + i0 + rowa],   rf1b = g_f1[bn + i0 + rowa + 1];
    const float rEpa = g_E1p[bn + i0 + rowa],  rEpb = g_E1p[bn + i0 + rowa + 1];
    const float rEna = g_E1n[bn + i0 + rowa],  rEnb = g_E1n[bn + i0 + rowa + 1];
    const uint8_t* adjba = (const uint8_t*)g_adjB + (size_t)(i0 + rowa) * 256 + oct;
    const uint8_t* adjbb = adjba + 256;
    const int doffa = rowa * SRD32 + oct * 4;
    const int doffb = doffa + SRD32;

    // ---- WhT cp.async staging identity: row tid>>1, half tid&1 (16 words) ----
    const uint32_t* whp = g_WhT32 + (((size_t)b * FF + (tid >> 1)) * NN >> 1) + (tid & 1) * 16;
    const int sdo = (tid >> 1) * SRD32 + (tid & 1) * 16;
    const uint32_t wdst[2] = { smem_u32(whts[0]) + sdo * 4, smem_u32(whts[1]) + sdo * 4 };

    // ---- mma identity: 8 warps as 2(M) x 4(N); warp tile 32 x 32 ----
    const int lane = tid & 31, wid = tid >> 5;
    const int mg = wid >> 2, ng = wid & 3;
    const int l4 = lane >> 2, lm = lane & 3;

    float acc[2][4][4] = {};
    float z0 = 0.f, z1 = 0.f;
    uint32_t ma, mb;

    __syncthreads();  // tables staged

    // ---- prologue: stage tile 0 ----
    #pragma unroll
    for (int ch = 0; ch < 4; ch++) cp_async16(wdst[0] + ch * 16, whp + ch * 4);
    asm volatile("cp.async.commit_group;");
    ma = adjba[0];
    mb = adjbb[0];
    build_u8_pair(ma, mb, ftab, ehtab, oct * 8, rf1a, rEpa, rEna, rf1b, rEpb, rEnb,
                  u_s[0] + doffa, u_s[0] + doffb, z0, z1);
    asm volatile("cp.async.wait_group 0;" ::: "memory");
    __syncthreads();

    for (int t = 0; t < 32; t++) {
        const int cur = t & 1, nxt = cur ^ 1;
        const int jb2 = (t + 1) * TJ;

        // ---- issue next tile's loads (async) ----
        if (t < 31) {
            #pragma unroll
            for (int ch = 0; ch < 4; ch++)
                cp_async16(wdst[nxt] + ch * 16, whp + (jb2 >> 1) + ch * 4);
            asm volatile("cp.async.commit_group;");
            ma = adjba[jb2 >> 3];
            mb = adjbb[jb2 >> 3];
        }

        // ---- mma(t): 2 k32 chunks x 2 k16 steps; conflict-free LDS.128 frags ----
        const uint32_t* wb = whts[cur];
        const uint32_t* ub = u_s[cur];
        #pragma unroll
        for (int ch = 0; ch < 2; ch++) {
            const int kc = ch * 16 + lm * 4;
            uint4 bv[4];
            #pragma unroll
            for (int ni = 0; ni < 4; ni++)
                bv[ni] = *(const uint4*)&wb[(ng * 32 + ni * 8 + l4) * SRD32 + kc];
            uint4 alo[2], ahi[2];
            #pragma unroll
            for (int mi = 0; mi < 2; mi++) {
                int row = mg * 32 + mi * 16 + l4;
                alo[mi] = *(const uint4*)&ub[row * SRD32 + kc];
                ahi[mi] = *(const uint4*)&ub[(row + 8) * SRD32 + kc];
            }
            #pragma unroll
            for (int mi = 0; mi < 2; mi++)    // k16 step 0
                #pragma unroll
                for (int ni = 0; ni < 4; ni++)
                    mma16(acc[mi][ni], alo[mi].x, ahi[mi].x, alo[mi].y, ahi[mi].y,
                          bv[ni].x, bv[ni].y);
            #pragma unroll
            for (int mi = 0; mi < 2; mi++)    // k16 step 1
                #pragma unroll
                for (int ni = 0; ni < 4; ni++)
                    mma16(acc[mi][ni], alo[mi].z, ahi[mi].z, alo[mi].w, ahi[mi].w,
                          bv[ni].z, bv[ni].w);
        }

        // ---- convert + store U(t+1) ----
        if (t < 31)
            build_u8_pair(ma, mb, ftab, ehtab, jb2 + oct * 8,
                          rf1a, rEpa, rEna, rf1b, rEpb, rEnb,
                          u_s[nxt] + doffa, u_s[nxt] + doffb, z0, z1);

        asm volatile("cp.async.wait_group 0;" ::: "memory");
        __syncthreads();
    }

    // ---- Z finalize: 8 octet-threads per row-pair are adjacent lanes ----
    #pragma unroll
    for (int o = 1; o < 8; o <<= 1) {
        z0 += __shfl_xor_sync(0xFFFFFFFFu, z0, o);
        z1 += __shfl_xor_sync(0xFFFFFFFFu, z1, o);
    }
    if (oct == 0) { z_s[rowa] = z0; z_s[rowa + 1] = z1; }
    __syncthreads();

    // ---- epilogue: 1/Z, +bias, ELU, store from fragments ----
    #pragma unroll
    for (int mi = 0; mi < 2; mi++) {
        const int r0 = mg * 32 + mi * 16 + l4;
        const float iz0 = 1.0f / z_s[r0];
        const float iz1 = 1.0f / z_s[r0 + 8];
        float* o0 = out + ((size_t)(bn + i0 + r0)) * FF;
        float* o1 = o0 + (size_t)8 * FF;
        #pragma unroll
        for (int ni = 0; ni < 4; ni++) {
            const int col = ng * 32 + ni * 8 + 2 * lm;
            const float b0 = bias_s[col], b1 = bias_s[col + 1];
            float x0 = acc[mi][ni][0] * iz0 + b0;
            float x1 = acc[mi][ni][1] * iz0 + b1;
            float x2 = acc[mi][ni][2] * iz1 + b0;
            float x3 = acc[mi][ni][3] * iz1 + b1;
            x0 = (x0 > 0.f) ? x0 : expm1f(x0);
            x1 = (x1 > 0.f) ? x1 : expm1f(x1);
            x2 = (x2 > 0.f) ? x2 : expm1f(x2);
            x3 = (x3 > 0.f) ? x3 : expm1f(x3);
            *(float2*)&o0[col] = make_float2(x0, x1);
            *(float2*)&o1[col] = make_float2(x2, x3);
        }
    }
}

// ============================== launch ==============================
extern "C" void kernel_launch(void* const* d_in, const int* in_sizes, int n_in,
                              void* d_out, int out_size) {
    const float* h    = (const float*)d_in[0];
    const float* adj  = (const float*)d_in[1];
    const float* W    = (const float*)d_in[2];
    const float* a    = (const float*)d_in[3];
    const float* bias = (const float*)d_in[4];
    float* out = (float*)d_out;

    const int smem1 = 65536 + 32768;
    cudaFuncSetAttribute(k1_gemm, cudaFuncAttributeMaxDynamicSharedMemorySize, smem1);
    cudaFuncSetAttribute(k3_main, cudaFuncAttributeMaxDynamicSharedMemorySize, K3_SMEM);

    // 256 row-octets x 64 groups = 16384 warps; 8 warps per 256-thread block
    k_adjB<<<(NN / 8) * (NN / 32) / 8, 256>>>(adj);
    k1_gemm<<<(BB * NN) / 64, 256, smem1>>>(h, W, a);
    k3_main<<<256, 256, K3_SMEM>>>(bias, out);
}

// round 17
// speedup vs baseline: 1.0932x; 1.0222x over previous
#include <cuda_runtime.h>
#include <cuda_fp16.h>
#include <math.h>
#include <stdint.h>

// Problem constants
#define BB 8
#define NN 2048
#define FF 128
#define TJ 64            // j-tile per iteration in k3
#define SRD32 48         // smem row stride (uint32): quad-stride 12 = 4 mod 8 -> conflict-free

typedef unsigned long long ull;

// -------- device scratch --------
__device__ uint32_t g_WhT32[BB * FF * NN / 2];  // [b][f][j/2] half2, sigma-permuted, 4MB
__device__ uint32_t g_adjB[NN * NN / 32];       // sigma-ordered adjacency bitmask, 512KB
__device__ float g_f1[BB * NN];
__device__ float g_f2[BB * NN];                 // j-permuted
__device__ float g_E1p[BB * NN];
__device__ float g_E1n[BB * NN];
__device__ uint32_t g_E2h2[BB * NN];            // j-permuted, half2(E2p, E2n)

// ======================= helpers =======================
__device__ __forceinline__ ull pk2(float lo, float hi) {
    ull d;
    asm("mov.b64 %0, {%1, %2};" : "=l"(d) : "r"(__float_as_uint(lo)), "r"(__float_as_uint(hi)));
    return d;
}
__device__ __forceinline__ void upk2(ull v, float& lo, float& hi) {
    unsigned a, b;
    asm("mov.b64 {%0, %1}, %2;" : "=r"(a), "=r"(b) : "l"(v));
    lo = __uint_as_float(a); hi = __uint_as_float(b);
}
__device__ __forceinline__ ull pfma(ull a, ull b, ull c) {
    ull d;
    asm("fma.rn.f32x2 %0, %1, %2, %3;" : "=l"(d) : "l"(a), "l"(b), "l"(c));
    return d;
}
// pack two f32 -> half2 (lo -> low half, hi -> high half)
__device__ __forceinline__ uint32_t pkhf(float lo, float hi) {
    __half2 t = __floats2half2_rn(lo, hi);
    return *reinterpret_cast<uint32_t*>(&t);
}
// m16n8k16 f16 MMA, fp32 accumulate
__device__ __forceinline__ void mma16(float* c, uint32_t a0, uint32_t a1, uint32_t a2,
                                      uint32_t a3, uint32_t b0, uint32_t b1) {
    asm volatile(
        "mma.sync.aligned.m16n8k16.row.col.f32.f16.f16.f32 "
        "{%0,%1,%2,%3}, {%4,%5,%6,%7}, {%8,%9}, {%0,%1,%2,%3};"
        : "+f"(c[0]), "+f"(c[1]), "+f"(c[2]), "+f"(c[3])
        : "r"(a0), "r"(a1), "r"(a2), "r"(a3), "r"(b0), "r"(b1));
}
__device__ __forceinline__ uint32_t smem_u32(const void* p) {
    uint32_t a;
    asm("{ .reg .u64 t; cvta.to.shared.u64 t, %1; cvt.u32.u64 %0, t; }" : "=r"(a) : "l"(p));
    return a;
}
__device__ __forceinline__ void cp_async16(uint32_t dst, const void* src) {
    asm volatile("cp.async.cg.shared.global [%0], [%1], 16;" :: "r"(dst), "l"(src));
}
// sigma: physical position of logical j within its 32-group (involution)
__device__ __forceinline__ int sigma32(int j) {
    return (j & ~31) | (8 * ((j >> 1) & 3) + 2 * ((j >> 3) & 3) + (j & 1));
}

// ===================== k1: WhT + f1/f2 + exp tables + adj bitmask, fused =====
// grid 256 (8 b x 32 row-tiles of 64), 256 threads, 2 CTAs/SM.
// adjB fusion: global warp g (0..2047) converts adj row g into 64 sigma-ordered
// ballot words, streamed with MLP=16 while the GEMM staging/loop hides latency.
__global__ __launch_bounds__(256, 2) void k1_gemm(const float* __restrict__ h,
                                                  const float* __restrict__ W,
                                                  const float* __restrict__ a,
                                                  const float* __restrict__ adj) {
    extern __shared__ char smem1[];
    float* Ws = (float*)smem1;            // 64KB (reused for score partials)
    float* hs = (float*)(smem1 + 65536);  // 32KB
    ull* part = (ull*)smem1;              // [64][32] score partials (overlay)

    int tid = threadIdx.x;
    const float* hb = h + (size_t)blockIdx.x * 64 * FF;

    // ---- stage W + h tiles (loads in flight) ----
    #pragma unroll
    for (int i = tid * 4; i < FF * FF; i += 1024)
        *(float4*)&Ws[i] = *(const float4*)&W[i];
    #pragma unroll
    for (int i = tid * 4; i < 64 * FF; i += 1024)
        *(float4*)&hs[i] = *(const float4*)&hb[i];

    // ---- fused adjB: warp g handles adj row g (4 batches of 16 groups) ----
    {
        const int gw = blockIdx.x * 8 + (tid >> 5);  // 0..2047 = adj row
        const int lane = tid & 31;
        const float* arow = adj + (size_t)gw * NN + sigma32(lane);
        #pragma unroll
        for (int g0 = 0; g0 < 4; g0++) {
            float v[16];
            #pragma unroll
            for (int g = 0; g < 16; g++)
                v[g] = __ldcs(&arow[(g0 * 16 + g) * 32]);
            uint32_t m[16];
            #pragma unroll
            for (int g = 0; g < 16; g++)
                m[g] = __ballot_sync(0xFFFFFFFFu, v[g] > 0.f);
            if (lane < 16) {
                uint32_t mv = m[0];
                #pragma unroll
                for (int r = 1; r < 16; r++) mv = (lane == r) ? m[r] : mv;
                g_adjB[gw * 64 + g0 * 16 + lane] = mv;
            }
        }
    }
    __syncthreads();

    int c0 = (tid & 31) * 4;
    int r0 = (tid >> 5) * 8;      // 8 consecutive j-rows
    ull accA[8], accB[8];
    #pragma unroll
    for (int r = 0; r < 8; r++) { accA[r] = 0ULL; accB[r] = 0ULL; }

    for (int k4 = 0; k4 < FF; k4 += 4) {
        ull wA[4], wB[4];
        #pragma unroll
        for (int s = 0; s < 4; s++) {
            float4 w = *(float4*)&Ws[(k4 + s) * FF + c0];
            wA[s] = pk2(w.x, w.y);
            wB[s] = pk2(w.z, w.w);
        }
        #pragma unroll
        for (int r = 0; r < 8; r++) {
            float4 hv = *(float4*)&hs[(r0 + r) * FF + k4];
            ull h0 = pk2(hv.x, hv.x), h1 = pk2(hv.y, hv.y);
            ull h2 = pk2(hv.z, hv.z), h3 = pk2(hv.w, hv.w);
            accA[r] = pfma(h0, wA[0], accA[r]);
            accB[r] = pfma(h0, wB[0], accB[r]);
            accA[r] = pfma(h1, wA[1], accA[r]);
            accB[r] = pfma(h1, wB[1], accB[r]);
            accA[r] = pfma(h2, wA[2], accA[r]);
            accB[r] = pfma(h2, wB[2], accB[r]);
            accA[r] = pfma(h3, wA[3], accA[r]);
            accB[r] = pfma(h3, wB[3], accB[r]);
        }
    }

    float f0[8], f1v[8], f2v[8], f3[8];
    #pragma unroll
    for (int r = 0; r < 8; r++) {
        upk2(accA[r], f0[r], f1v[r]);
        upk2(accB[r], f2v[r], f3[r]);
    }

    // ---- score partials: sp[r] = sum_e Wh[row][c0+e] * (a1[c0+e], a2[c0+e]) ----
    ull apair[4];
    #pragma unroll
    for (int e = 0; e < 4; e++) apair[e] = pk2(a[c0 + e], a[FF + c0 + e]);
    ull sp[8];
    #pragma unroll
    for (int r = 0; r < 8; r++) {
        ull s = pfma(pk2(f0[r], f0[r]), apair[0], 0ULL);
        s = pfma(pk2(f1v[r], f1v[r]), apair[1], s);
        s = pfma(pk2(f2v[r], f2v[r]), apair[2], s);
        s = pfma(pk2(f3[r], f3[r]), apair[3], s);
        sp[r] = s;
    }

    __syncthreads();  // all threads done reading Ws before overlay
    #pragma unroll
    for (int r = 0; r < 8; r++)
        part[(r0 + r) * 32 + (tid & 31)] = sp[r];

    // ---- WhT global store (no smem involved) ----
    int b = blockIdx.x >> 5;
    int n0 = (blockIdx.x & 31) * 64;
    int bofs = (r0 & 31) >> 3;
    size_t grp32 = ((size_t)(n0 + (r0 & ~31))) >> 1;
    #pragma unroll
    for (int e = 0; e < 4; e++) {
        const float* fe = (e == 0) ? f0 : (e == 1) ? f1v : (e == 2) ? f2v : f3;
        uint32_t* dst = g_WhT32 + (((size_t)b * FF + c0 + e) * NN >> 1) + grp32 + bofs;
        #pragma unroll
        for (int s = 0; s < 4; s++)
            dst[4 * s] = pkhf(fe[2 * s], fe[2 * s + 1]);
    }

    __syncthreads();  // partials visible

    // ---- reduce 32 lanes per row; exps; store score tables ----
    if (tid < 64) {
        const ull* pr = part + tid * 32;
        float s1 = 0.f, s2 = 0.f;
        #pragma unroll
        for (int l = 0; l < 32; l++) {
            float lo, hi;
            upk2(pr[l], lo, hi);
            s1 += lo;
            s2 += hi;
        }
        int rowg = b * NN + n0 + tid;
        g_f1[rowg]  = s1;
        g_E1p[rowg] = expf(s1);
        g_E1n[rowg] = expf(0.2f * s1);
        int pj = b * NN + sigma32(n0 + tid);
        g_f2[pj]   = s2;
        g_E2h2[pj] = pkhf(expf(s2), expf(0.2f * s2));
    }
}

// ===================== k3: pipelined f16 mma masked-attention GEMM ===========
// 256 threads / 8 warps / 64 i-rows per CTA; 2 CTAs per SM; grid 256.
// smem (uint32 words): whts0@0(6144), whts1@6144, u0@12288(3072), u1@15360,
// ftab@18432(2048), ehtab@20480(2048), z@22528(64), bias@22592(128); tot 22720
#define K3_SMEM (22720 * 4)

// build masked-exp U for TWO rows x 8 phys-j (shared table loads); bit masks
__device__ __forceinline__ void build_u8_pair(
    uint32_t ma, uint32_t mb, const float* ftab, const uint32_t* ehtab, int joff,
    float rf1a, float rEpa, float rEna, float rf1b, float rEpb, float rEnb,
    uint32_t* da, uint32_t* db, float& za, float& zb) {
    uint32_t pka[4], pkb[4];
    #pragma unroll
    for (int g = 0; g < 2; g++) {
        float4 f = *(const float4*)&ftab[joff + g * 4];
        uint4 eh = *(const uint4*)&ehtab[joff + g * 4];
        float ua[4], ub[4];
        #pragma unroll
        for (int e = 0; e < 4; e++) {
            float2 pe = __half22float2(*reinterpret_cast<__half2*>(&(&eh.x)[e]));
            float fv = (&f.x)[e];
            float va = (rf1a + fv > 0.f) ? (rEpa * pe.x) : (rEna * pe.y);
            float vb = (rf1b + fv > 0.f) ? (rEpb * pe.x) : (rEnb * pe.y);
            ua[e] = ((ma >> (g * 4 + e)) & 1u) ? va : 0.f;
            ub[e] = ((mb >> (g * 4 + e)) & 1u) ? vb : 0.f;
        }
        pka[2 * g]     = pkhf(ua[0], ua[1]);
        pka[2 * g + 1] = pkhf(ua[2], ua[3]);
        pkb[2 * g]     = pkhf(ub[0], ub[1]);
        pkb[2 * g + 1] = pkhf(ub[2], ub[3]);
    }
    #pragma unroll
    for (int q = 0; q < 4; q++) {  // sum the fp16-rounded values
        float2 fa = __half22float2(*reinterpret_cast<__half2*>(&pka[q]));
        float2 fb = __half22float2(*reinterpret_cast<__half2*>(&pkb[q]));
        za += fa.x + fa.y;
        zb += fb.x + fb.y;
    }
    *(uint4*)da = make_uint4(pka[0], pka[1], pka[2], pka[3]);
    *(uint4*)db = make_uint4(pkb[0], pkb[1], pkb[2], pkb[3]);
}

__global__ __launch_bounds__(256, 2) void k3_main(const float* __restrict__ bias,
                                                  float* __restrict__ out) {
    extern __shared__ uint32_t smw[];
    uint32_t* whts[2] = { smw, smw + 6144 };
    uint32_t* u_s[2]  = { smw + 12288, smw + 15360 };
    float* ftab      = (float*)(smw + 18432);
    uint32_t* ehtab  = smw + 20480;
    float* z_s       = (float*)(smw + 22528);
    float* bias_s    = (float*)(smw + 22592);

    const int tid = threadIdx.x;
    const int b = blockIdx.x >> 5;
    const int i0 = (blockIdx.x & 31) * 64;
    const int bn = b * NN;

    // ---- per-CTA tables (whole permuted 2048-j range, loaded once) ----
    #pragma unroll
    for (int i = tid * 4; i < NN; i += 1024) {
        *(float4*)&ftab[i] = *(const float4*)&g_f2[bn + i];
        *(uint4*)&ehtab[i] = *(const uint4*)&g_E2h2[bn + i];
    }
    if (tid < 128) bias_s[tid] = bias[tid];

    // ---- builder identity: 2 rows, one 8-phys-j octet of the 64-j tile ----
    const int rp = tid >> 3;          // 0..31 (row pair)
    const int oct = tid & 7;          // 0..7
    const int rowa = 2 * rp;
    const float rf1a = g_f1[bn + i0 + rowa],   rf1b = g_f1[bn + i0 + rowa + 1];
    const float rEpa = g_E1p[bn + i0 + rowa],  rEpb = g_E1p[bn + i0 + rowa + 1];
    const float rEna = g_E1n[bn + i0 + rowa],  rEnb = g_E1n[bn + i0 + rowa + 1];
    const uint8_t* adjba = (const uint8_t*)g_adjB + (size_t)(i0 + rowa) * 256 + oct;
    const uint8_t* adjbb = adjba + 256;
    const int doffa = rowa * SRD32 + oct * 4;
    const int doffb = doffa + SRD32;

    // ---- WhT cp.async staging identity: row tid>>1, half tid&1 (16 words) ----
    const uint32_t* whp = g_WhT32 + (((size_t)b * FF + (tid >> 1)) * NN >> 1) + (tid & 1) * 16;
    const int sdo = (tid >> 1) * SRD32 + (tid & 1) * 16;
    const uint32_t wdst[2] = { smem_u32(whts[0]) + sdo * 4, smem_u32(whts[1]) + sdo * 4 };

    // ---- mma identity: 8 warps as 2(M) x 4(N); warp tile 32 x 32 ----
    const int lane = tid & 31, wid = tid >> 5;
    const int mg = wid >> 2, ng = wid & 3;
    const int l4 = lane >> 2, lm = lane & 3;

    float acc[2][4][4] = {};
    float z0 = 0.f, z1 = 0.f;
    uint32_t ma, mb;

    __syncthreads();  // tables staged

    // ---- prologue: stage tile 0 ----
    #pragma unroll
    for (int ch = 0; ch < 4; ch++) cp_async16(wdst[0] + ch * 16, whp + ch * 4);
    asm volatile("cp.async.commit_group;");
    ma = adjba[0];
    mb = adjbb[0];
    build_u8_pair(ma, mb, ftab, ehtab, oct * 8, rf1a, rEpa, rEna, rf1b, rEpb, rEnb,
                  u_s[0] + doffa, u_s[0] + doffb, z0, z1);
    asm volatile("cp.async.wait_group 0;" ::: "memory");
    __syncthreads();

    for (int t = 0; t < 32; t++) {
        const int cur = t & 1, nxt = cur ^ 1;
        const int jb2 = (t + 1) * TJ;

        // ---- issue next tile's loads (async) ----
        if (t < 31) {
            #pragma unroll
            for (int ch = 0; ch < 4; ch++)
                cp_async16(wdst[nxt] + ch * 16, whp + (jb2 >> 1) + ch * 4);
            asm volatile("cp.async.commit_group;");
            ma = adjba[jb2 >> 3];
            mb = adjbb[jb2 >> 3];
        }

        // ---- mma(t): 2 k32 chunks x 2 k16 steps; conflict-free LDS.128 frags ----
        const uint32_t* wb = whts[cur];
        const uint32_t* ub = u_s[cur];
        #pragma unroll
        for (int ch = 0; ch < 2; ch++) {
            const int kc = ch * 16 + lm * 4;
            uint4 bv[4];
            #pragma unroll
            for (int ni = 0; ni < 4; ni++)
                bv[ni] = *(const uint4*)&wb[(ng * 32 + ni * 8 + l4) * SRD32 + kc];
            uint4 alo[2], ahi[2];
            #pragma unroll
            for (int mi = 0; mi < 2; mi++) {
                int row = mg * 32 + mi * 16 + l4;
                alo[mi] = *(const uint4*)&ub[row * SRD32 + kc];
                ahi[mi] = *(const uint4*)&ub[(row + 8) * SRD32 + kc];
            }
            #pragma unroll
            for (int mi = 0; mi < 2; mi++)    // k16 step 0
                #pragma unroll
                for (int ni = 0; ni < 4; ni++)
                    mma16(acc[mi][ni], alo[mi].x, ahi[mi].x, alo[mi].y, ahi[mi].y,
                          bv[ni].x, bv[ni].y);
            #pragma unroll
            for (int mi = 0; mi < 2; mi++)    // k16 step 1
                #pragma unroll
                for (int ni = 0; ni < 4; ni++)
                    mma16(acc[mi][ni], alo[mi].z, ahi[mi].z, alo[mi].w, ahi[mi].w,
                          bv[ni].z, bv[ni].w);
        }

        // ---- convert + store U(t+1) ----
        if (t < 31)
            build_u8_pair(ma, mb, ftab, ehtab, jb2 + oct * 8,
                          rf1a, rEpa, rEna, rf1b, rEpb, rEnb,
                          u_s[nxt] + doffa, u_s[nxt] + doffb, z0, z1);

        asm volatile("cp.async.wait_group 0;" ::: "memory");
        __syncthreads();
    }

    // ---- Z finalize: 8 octet-threads per row-pair are adjacent lanes ----
    #pragma unroll
    for (int o = 1; o < 8; o <<= 1) {
        z0 += __shfl_xor_sync(0xFFFFFFFFu, z0, o);
        z1 += __shfl_xor_sync(0xFFFFFFFFu, z1, o);
    }
    if (oct == 0) { z_s[rowa] = z0; z_s[rowa + 1] = z1; }
    __syncthreads();

    // ---- epilogue: 1/Z, +bias, ELU, store from fragments ----
    #pragma unroll
    for (int mi = 0; mi < 2; mi++) {
        const int r0 = mg * 32 + mi * 16 + l4;
        const float iz0 = 1.0f / z_s[r0];
        const float iz1 = 1.0f / z_s[r0 + 8];
        float* o0 = out + ((size_t)(bn + i0 + r0)) * FF;
        float* o1 = o0 + (size_t)8 * FF;
        #pragma unroll
        for (int ni = 0; ni < 4; ni++) {
            const int col = ng * 32 + ni * 8 + 2 * lm;
            const float b0 = bias_s[col], b1 = bias_s[col + 1];
            float x0 = acc[mi][ni][0] * iz0 + b0;
            float x1 = acc[mi][ni][1] * iz0 + b1;
            float x2 = acc[mi][ni][2] * iz1 + b0;
            float x3 = acc[mi][ni][3] * iz1 + b1;
            x0 = (x0 > 0.f) ? x0 : expm1f(x0);
            x1 = (x1 > 0.f) ? x1 : expm1f(x1);
            x2 = (x2 > 0.f) ? x2 : expm1f(x2);
            x3 = (x3 > 0.f) ? x3 : expm1f(x3);
            *(float2*)&o0[col] = make_float2(x0, x1);
            *(float2*)&o1[col] = make_float2(x2, x3);
        }
    }
}

// ============================== launch ==============================
extern "C" void kernel_launch(void* const* d_in, const int* in_sizes, int n_in,
                              void* d_out, int out_size) {
    const float* h    = (const float*)d_in[0];
    const float* adj  = (const float*)d_in[1];
    const float* W    = (const float*)d_in[2];
    const float* a    = (const float*)d_in[3];
    const float* bias = (const float*)d_in[4];
    float* out = (float*)d_out;

    const int smem1 = 65536 + 32768;
    cudaFuncSetAttribute(k1_gemm, cudaFuncAttributeMaxDynamicSharedMemorySize, smem1);
    cudaFuncSetAttribute(k3_main, cudaFuncAttributeMaxDynamicSharedMemorySize, K3_SMEM);

    k1_gemm<<<(BB * NN) / 64, 256, smem1>>>(h, W, a, adj);
    k3_main<<<256, 256, K3_SMEM>>>(bias, out);
}